// round 15
// baseline (speedup 1.0000x reference)
#include <cuda_runtime.h>
#include <math.h>
#include <stdint.h>

// Problem constants (fixed by setup_inputs)
#define BB 8
#define NN 100
#define HWD 25600
#define KCLS 80
#define TT 160
#define MT 20
#define BNR (BB*NN)            // 800

// GEMM config
#define SPLITS 21
#define BKF 32                 // fp32 K per chunk
#define NCH (HWD/BKF)          // 800 chunks total

// Scratch (allocation-free rule: __device__ globals)
__device__ float g_part[SPLITS*BNR*TT];   // split-K partial dot products
__device__ float g_pnp[SPLITS*BNR];       // per-split pred-norm partials
__device__ float g_tnp[SPLITS*TT];        // per-split target-norm partials

// ---------------------------------------------------------------------------
// 3xTF32 mma.sync GEMM + fused norm partials, double-buffered smem.
// CTA tile 128(M) x 160(N) x 32(K). 512 threads, 16 warps = 4m x 4n.
// (Exact Round-9/11 configuration — best measured.)
// ---------------------------------------------------------------------------
#define STG_WORDS 20736         // words per stage (82,944 B)
#define SM_AH 0
#define SM_AL 4608              // 128*36
#define SM_BH 9216
#define SM_BL 14976             // + 160*36
#define SMEM_BYTES (2*STG_WORDS*4)   // 165,888 B

__device__ __forceinline__ void tf32_split(float f, uint32_t& h, uint32_t& l)
{
    asm("cvt.rna.tf32.f32 %0, %1;" : "=r"(h) : "f"(f));
    float r = f - __uint_as_float(h);
    asm("cvt.rna.tf32.f32 %0, %1;" : "=r"(l) : "f"(r));
}

#define MMA1688(d, a, b0, b1) \
    asm volatile("mma.sync.aligned.m16n8k8.row.col.f32.tf32.tf32.f32 " \
        "{%0,%1,%2,%3}, {%4,%5,%6,%7}, {%8,%9}, {%0,%1,%2,%3};" \
        : "+f"((d)[0]), "+f"((d)[1]), "+f"((d)[2]), "+f"((d)[3]) \
        : "r"((a)[0]), "r"((a)[1]), "r"((a)[2]), "r"((a)[3]), "r"(b0), "r"(b1))

__global__ void __launch_bounds__(512, 1) gemm_tf32(const float* __restrict__ A,
                                                     const float* __restrict__ Bm)
{
    extern __shared__ __align__(16) uint32_t sm[];

    const int tid = threadIdx.x;
    const int wid = tid >> 5, lane = tid & 31;
    const int wm = wid >> 2, wn = wid & 3;
    const int lr = lane >> 2, lc = lane & 3;

    const int row0 = blockIdx.x * 128;
    const int z = blockIdx.y;
    const int cbeg = (z * NCH) / SPLITS;
    const int cend = ((z + 1) * NCH) / SPLITS;

    const int r8 = tid >> 3;       // 0..63
    const int q  = tid & 7;        // float4 quad within 32-wide K
    const bool bact3 = (tid < 256);
    const bool doB = (blockIdx.x == 0);

    float4 pa[2], pb[3];
    float asq[2] = {0.f, 0.f};
    float bsq[3] = {0.f, 0.f, 0.f};

    auto LDG = [&](int c) {
        size_t kb = (size_t)c * BKF;
        #pragma unroll
        for (int i = 0; i < 2; i++) {
            int gr = row0 + r8 + 64 * i;
            pa[i] = (gr < BNR) ? *(const float4*)(A + (size_t)gr * HWD + kb + q * 4)
                               : make_float4(0,0,0,0);
        }
        #pragma unroll
        for (int i = 0; i < 2; i++) {
            int gb = r8 + 64 * i;
            pb[i] = *(const float4*)(Bm + (size_t)gb * HWD + kb + q * 4);
        }
        pb[2] = bact3 ? *(const float4*)(Bm + (size_t)(r8 + 128) * HWD + kb + q * 4)
                      : make_float4(0,0,0,0);
    };

    auto CVTST = [&](int st) {
        uint32_t* s = sm + st * STG_WORDS;
        #pragma unroll
        for (int i = 0; i < 2; i++) {
            float4 v = pa[i];
            asq[i] += v.x*v.x + v.y*v.y + v.z*v.z + v.w*v.w;
            uint4 hv, lv;
            tf32_split(v.x, hv.x, lv.x); tf32_split(v.y, hv.y, lv.y);
            tf32_split(v.z, hv.z, lv.z); tf32_split(v.w, hv.w, lv.w);
            int ar = r8 + 64 * i;
            *(uint4*)(s + SM_AH + ar * 36 + q * 4) = hv;
            *(uint4*)(s + SM_AL + ar * 36 + q * 4) = lv;
        }
        #pragma unroll
        for (int i = 0; i < 3; i++) {
            if (i == 2 && !bact3) break;
            float4 v = pb[i];
            bsq[i] += v.x*v.x + v.y*v.y + v.z*v.z + v.w*v.w;
            uint4 hv, lv;
            tf32_split(v.x, hv.x, lv.x); tf32_split(v.y, hv.y, lv.y);
            tf32_split(v.z, hv.z, lv.z); tf32_split(v.w, hv.w, lv.w);
            int br = r8 + 64 * i;
            *(uint4*)(s + SM_BH + br * 36 + q * 4) = hv;
            *(uint4*)(s + SM_BL + br * 36 + q * 4) = lv;
        }
    };

    float acc[2][5][4];
    #pragma unroll
    for (int f = 0; f < 2; f++)
        #pragma unroll
        for (int nf = 0; nf < 5; nf++)
            #pragma unroll
            for (int e = 0; e < 4; e++) acc[f][nf][e] = 0.f;

    auto COMP = [&](int st) {
        uint32_t* s = sm + st * STG_WORDS;
        #pragma unroll
        for (int ks = 0; ks < 4; ks++) {
            int k0 = ks * 8;
            uint32_t ah[2][4], al[2][4];
            #pragma unroll
            for (int f = 0; f < 2; f++) {
                int m0 = wm * 32 + f * 16 + lr;
                ah[f][0] = s[SM_AH + (m0    ) * 36 + k0 + lc];
                ah[f][1] = s[SM_AH + (m0 + 8) * 36 + k0 + lc];
                ah[f][2] = s[SM_AH + (m0    ) * 36 + k0 + lc + 4];
                ah[f][3] = s[SM_AH + (m0 + 8) * 36 + k0 + lc + 4];
                al[f][0] = s[SM_AL + (m0    ) * 36 + k0 + lc];
                al[f][1] = s[SM_AL + (m0 + 8) * 36 + k0 + lc];
                al[f][2] = s[SM_AL + (m0    ) * 36 + k0 + lc + 4];
                al[f][3] = s[SM_AL + (m0 + 8) * 36 + k0 + lc + 4];
            }
            #pragma unroll
            for (int nf = 0; nf < 5; nf++) {
                int n0 = wn * 40 + nf * 8 + lr;
                uint32_t bh0 = s[SM_BH + n0 * 36 + k0 + lc];
                uint32_t bh1 = s[SM_BH + n0 * 36 + k0 + lc + 4];
                uint32_t bl0 = s[SM_BL + n0 * 36 + k0 + lc];
                uint32_t bl1 = s[SM_BL + n0 * 36 + k0 + lc + 4];
                #pragma unroll
                for (int f = 0; f < 2; f++) {
                    MMA1688(acc[f][nf], ah[f], bh0, bh1);
                    MMA1688(acc[f][nf], ah[f], bl0, bl1);
                    MMA1688(acc[f][nf], al[f], bh0, bh1);
                }
            }
        }
    };

    LDG(cbeg);
    CVTST(0);
    __syncthreads();

    for (int c = cbeg; c < cend; c++) {
        int st = (c - cbeg) & 1;
        bool more = (c + 1 < cend);
        if (more) LDG(c + 1);
        COMP(st);
        if (more) CVTST(st ^ 1);
        __syncthreads();
    }

    #pragma unroll
    for (int i = 0; i < 2; i++) {
        float sv = asq[i];
        #pragma unroll
        for (int o = 4; o; o >>= 1) sv += __shfl_down_sync(0xffffffffu, sv, o, 8);
        if (q == 0) {
            int gr = row0 + r8 + 64 * i;
            if (gr < BNR) g_pnp[z * BNR + gr] = sv;
        }
    }
    if (doB) {
        #pragma unroll
        for (int i = 0; i < 3; i++) {
            if (i == 2 && !bact3) break;
            float sv = bsq[i];
            #pragma unroll
            for (int o = 4; o; o >>= 1) sv += __shfl_down_sync(0xffffffffu, sv, o, 8);
            if (q == 0) g_tnp[z * TT + r8 + 64 * i] = sv;
        }
    }

    #pragma unroll
    for (int f = 0; f < 2; f++) {
        int grow0 = row0 + wm * 32 + f * 16 + lr;
        #pragma unroll
        for (int nf = 0; nf < 5; nf++) {
            int col = wn * 40 + nf * 8 + lc * 2;
            if (grow0 < BNR) {
                float* o = g_part + ((size_t)z * BNR + grow0) * TT + col;
                o[0] = acc[f][nf][0]; o[1] = acc[f][nf][1];
            }
            if (grow0 + 8 < BNR) {
                float* o = g_part + ((size_t)z * BNR + grow0 + 8) * TT + col;
                o[0] = acc[f][nf][2]; o[1] = acc[f][nf][3];
            }
        }
    }
}

// ---------------------------------------------------------------------------
// Shared element-cost function: MUST be arithmetically identical between the
// assemble path and the hungarian slice path (bit-identical C).
// ---------------------------------------------------------------------------
__device__ __forceinline__ float elem_cost(float dot, float den, float x)
{
    float score = -((2.f * dot + 1e-4f) / (den + 1e-4f));
    float pp = 1.f / (1.f + expf(-x));
    float neg = 0.75f * pp * pp * (-logf(1.f - pp + 1e-8f));
    float pos = 0.25f * (1.f - pp) * (1.f - pp) * (-logf(pp + 1e-8f));
    float c = 2.f * score + (pos - neg);
    if (!isfinite(c)) c = 0.f;
    return c;
}

// ---------------------------------------------------------------------------
// Fused tail: blocks 0..124 assemble the full C; blocks 125..132 run the
// per-image Hungarian, each first computing its own 20x100 cost slice from
// g_part/g_pnp/g_tnp/logits with identical arithmetic (so it matches the C
// written by the assemble blocks), then warp 0 runs JV.
// Hungarian no longer waits for assemble — both start at gemm completion.
// ---------------------------------------------------------------------------
__device__ __forceinline__ uint32_t f2k(float x)
{
    int b = __float_as_int(x);
    return (uint32_t)b ^ ((b < 0) ? 0xFFFFFFFFu : 0x80000000u);
}
__device__ __forceinline__ float k2f(uint32_t k)
{
    int b = (int)(k ^ (((int)k < 0) ? 0x80000000u : 0xFFFFFFFFu));
    return __int_as_float(b);
}

__global__ void tail_kernel(const float* __restrict__ logits,
                            const int* __restrict__ tgt_ids,
                            float* __restrict__ out)
{
    const int tid = threadIdx.x;

    if (blockIdx.x < 125) {
        // ================= assemble =================
        __shared__ float s_tn[TT];
        __shared__ float s_pn[8];

        int b0 = blockIdx.x * 256;           // t4-index base; covers 32000 exactly
        int rowlo = b0 / (TT/4);

        if (tid < TT) {
            float s = 0.f;
            #pragma unroll
            for (int z = 0; z < SPLITS; z++) s += g_tnp[z * TT + tid];
            s_tn[tid] = s;
        } else if (tid < TT + 8) {
            int r = rowlo + (tid - TT);
            float s = 0.f;
            if (r < BNR) {
                #pragma unroll
                for (int z = 0; z < SPLITS; z++) s += g_pnp[z * BNR + r];
            }
            s_pn[tid - TT] = s;
        }
        __syncthreads();

        int idx = b0 + tid;
        int row = idx / (TT/4), t4 = idx % (TT/4);

        float4 dot = make_float4(0.f, 0.f, 0.f, 0.f);
        #pragma unroll
        for (int s = 0; s < SPLITS; s++) {
            float4 v = *(const float4*)(g_part + ((size_t)s * BNR + row) * TT + t4 * 4);
            dot.x += v.x; dot.y += v.y; dot.z += v.z; dot.w += v.w;
        }
        float pn = s_pn[row - rowlo];
        const float* lrow = logits + row * KCLS;

        float4 res;
        float* dp = (float*)&dot;
        float* rp = (float*)&res;
        #pragma unroll
        for (int e = 0; e < 4; e++) {
            int t = t4 * 4 + e;
            rp[e] = elem_cost(dp[e], pn + s_tn[t], lrow[tgt_ids[t]]);
        }
        *(float4*)(out + (size_t)row * TT + t4 * 4) = res;
        return;
    }

    // ================= hungarian =================
    int b = blockIdx.x - 125;
    int lane = tid & 31;

    __shared__ float cost[MT][NN];
    __shared__ float pn[NN], tn[MT];
    __shared__ float u[MT+1];
    __shared__ float w[NN+1];            // w[j] = u[p[j]]
    __shared__ int p[NN+1], way[NN+1];

    // --- norms for this image (same z-order as assemble) ---
    if (tid < NN) {
        int row = b * NN + tid;
        float s = 0.f;
        #pragma unroll
        for (int z = 0; z < SPLITS; z++) s += g_pnp[z * BNR + row];
        pn[tid] = s;
    } else if (tid < NN + MT) {
        int t = b * MT + (tid - NN);
        float s = 0.f;
        #pragma unroll
        for (int z = 0; z < SPLITS; z++) s += g_tnp[z * TT + t];
        tn[tid - NN] = s;
    }
    __syncthreads();

    // --- cost slice: 2000 entries across 256 threads, identical arithmetic ---
    for (int idx = tid; idx < MT * NN; idx += 256) {
        int r = idx / NN;                 // target within image
        int c = idx % NN;                 // pred within image
        int row = b * NN + c;
        int t = b * MT + r;
        float dotv = 0.f;
        #pragma unroll
        for (int z = 0; z < SPLITS; z++)
            dotv += g_part[((size_t)z * BNR + row) * TT + t];
        cost[r][c] = elem_cost(dotv, pn[c] + tn[r], logits[row * KCLS + tgt_ids[t]]);
    }
    __syncthreads();

    if (tid >= 32) return;

    // --- JV (unchanged from Round 9/11) ---
    for (int j = lane; j <= NN; j += 32) { p[j] = 0; way[j] = 0; w[j] = 0.f; }
    for (int j = lane; j <= MT; j += 32) u[j] = 0.0f;
    float v[4] = {0.f, 0.f, 0.f, 0.f};
    const int jcol[4] = {lane + 1, lane + 33, lane + 65, lane + 97};
    const uint32_t KINF = 0xFFFFFFFFu;
    __syncwarp();

    for (int i = 1; i <= MT; i++) {
        if (lane == 0) { p[0] = i; w[0] = u[i]; }
        uint32_t absk[4] = {KINF, KINF, KINF, KINF};
        float dj[4] = {0.f, 0.f, 0.f, 0.f};
        int usedm = (lane >= 4) ? 8 : 0;       // kk=3 invalid for lane>=4 (j>100)
        float Dprev = 0.f;
        int j0 = 0;
        __syncwarp();

        while (true) {
            if (j0 > 0) {
                int ol = (j0 - 1) & 31, ok = (j0 - 1) >> 5;
                if (lane == ol) {
                    #pragma unroll
                    for (int kk = 0; kk < 4; kk++)
                        if (kk == ok) { usedm |= 1 << kk; dj[kk] = Dprev; }
                }
            }
            int i0 = p[j0];                 // independent loads -> pipelined
            float off = Dprev - w[j0];

            #pragma unroll
            for (int kk = 0; kk < 4; kk++) {
                if (!((usedm >> kk) & 1)) {
                    float cur = (cost[i0 - 1][jcol[kk] - 1] - v[kk]) + off;
                    uint32_t ck = f2k(cur);
                    if (ck < absk[kk]) { absk[kk] = ck; way[jcol[kk]] = j0; }
                }
            }

            uint32_t bk = KINF;
            uint32_t bj = NN + 2;
            #pragma unroll
            for (int kk = 0; kk < 4; kk++) {
                if (!((usedm >> kk) & 1) && absk[kk] < bk) {
                    bk = absk[kk]; bj = (uint32_t)jcol[kk];
                }
            }
            uint32_t kmin = __reduce_min_sync(0xffffffffu, bk);
            uint32_t j1 = __reduce_min_sync(0xffffffffu, (bk == kmin) ? bj : 0x7FFFFFFFu);

            Dprev = k2f(kmin);            // S_k = abs[j1]
            j0 = (int)j1;
            if (p[j0] == 0) break;
        }

        float Slast = Dprev;
        if (lane == 0) u[i] += Slast;
        #pragma unroll
        for (int kk = 0; kk < 4; kk++) {
            if (((usedm >> kk) & 1) && !(kk == 3 && lane >= 4)) {
                float du = Slast - dj[kk];
                int r = p[jcol[kk]];       // distinct rows across lanes
                u[r] += du;
                v[kk] -= du;
            }
        }
        __syncwarp();
        if (lane == 0) {                  // augment along way[] chain
            int jj = j0;
            while (jj) { int jp = way[jj]; p[jj] = p[jp]; jj = jp; }
        }
        __syncwarp();
        #pragma unroll
        for (int kk = 0; kk < 4; kk++) {
            if (!(kk == 3 && lane >= 4)) {
                int pj = p[jcol[kk]];
                w[jcol[kk]] = u[pj];       // u[0] == 0 for unassigned
            }
        }
        __syncwarp();
    }

    if (lane == 0) {
        int k = 0;
        for (int j = 1; j <= NN; j++) {
            if (p[j] != 0) {
                out[(size_t)BNR*TT + b*MT + k]            = (float)(j - 1);
                out[(size_t)BNR*TT + BB*MT + b*MT + k]    = (float)(p[j] - 1);
                k++;
            }
        }
    }
}

// ---------------------------------------------------------------------------
extern "C" void kernel_launch(void* const* d_in, const int* in_sizes, int n_in,
                              void* d_out, int out_size)
{
    const float* pred_masks   = (const float*)d_in[0];   // (8,100,160,160)
    const float* pred_logits  = (const float*)d_in[1];   // (8,100,80)
    const float* target_masks = (const float*)d_in[2];   // (160,160,160)
    const int*   tgt_ids      = (const int*)d_in[3];     // (160,)
    float* out = (float*)d_out;                           // C(128000) | rows(160) | cols(160)

    cudaFuncSetAttribute(gemm_tf32, cudaFuncAttributeMaxDynamicSharedMemorySize,
                         SMEM_BYTES);

    gemm_tf32<<<dim3(7, SPLITS), 512, SMEM_BYTES>>>(pred_masks, target_masks);

    tail_kernel<<<133, 256>>>(pred_logits, tgt_ids, out);
}

// round 16
// speedup vs baseline: 1.1457x; 1.1457x over previous
#include <cuda_runtime.h>
#include <math.h>
#include <stdint.h>

// Problem constants (fixed by setup_inputs)
#define BB 8
#define NN 100
#define HWD 25600
#define KCLS 80
#define TT 160
#define MT 20
#define BNR (BB*NN)            // 800

// GEMM config
#define SPLITS 21
#define BKF 32                 // fp32 K per chunk
#define NCH (HWD/BKF)          // 800 chunks total

// Scratch (allocation-free rule: __device__ globals)
__device__ float g_part[SPLITS*BNR*TT];   // split-K partial dot products
__device__ float g_pnp[SPLITS*BNR];       // per-split pred-norm partials
__device__ float g_tnp[SPLITS*TT];        // per-split target-norm partials
__device__ float g_pnorm[BNR];
__device__ float g_tnorm[TT];

// ---------------------------------------------------------------------------
// 3xTF32 mma.sync GEMM + fused norm partials, double-buffered smem.
// CTA tile 128(M) x 160(N) x 32(K). 256 threads, 8 warps = 4m x 2n.
// Warp tile 32x80 (2 m-frags x 10 n-frags) — the R4 shape, best-measured
// gemm (126.6us), now with the R9 single-sync double-buffer + norm fusion.
// LDS-per-MMA = (16+40)/60 = 0.93 vs 1.2 for the 5-nf shape.
// ---------------------------------------------------------------------------
#define STG_WORDS 20736         // words per stage (82,944 B)
#define SM_AH 0
#define SM_AL 4608              // 128*36
#define SM_BH 9216
#define SM_BL 14976             // + 160*36
#define SMEM_BYTES (2*STG_WORDS*4)   // 165,888 B

__device__ __forceinline__ void tf32_split(float f, uint32_t& h, uint32_t& l)
{
    asm("cvt.rna.tf32.f32 %0, %1;" : "=r"(h) : "f"(f));
    float r = f - __uint_as_float(h);
    asm("cvt.rna.tf32.f32 %0, %1;" : "=r"(l) : "f"(r));
}

#define MMA1688(d, a, b0, b1) \
    asm volatile("mma.sync.aligned.m16n8k8.row.col.f32.tf32.tf32.f32 " \
        "{%0,%1,%2,%3}, {%4,%5,%6,%7}, {%8,%9}, {%0,%1,%2,%3};" \
        : "+f"((d)[0]), "+f"((d)[1]), "+f"((d)[2]), "+f"((d)[3]) \
        : "r"((a)[0]), "r"((a)[1]), "r"((a)[2]), "r"((a)[3]), "r"(b0), "r"(b1))

__global__ void __launch_bounds__(256, 1) gemm_tf32(const float* __restrict__ A,
                                                     const float* __restrict__ Bm)
{
    extern __shared__ __align__(16) uint32_t sm[];

    const int tid = threadIdx.x;
    const int wid = tid >> 5, lane = tid & 31;
    const int wm = wid >> 1, wn = wid & 1;
    const int lr = lane >> 2, lc = lane & 3;

    const int row0 = blockIdx.x * 128;
    const int z = blockIdx.y;
    const int cbeg = (z * NCH) / SPLITS;
    const int cend = ((z + 1) * NCH) / SPLITS;

    const int r8 = tid >> 3;       // 0..31
    const int q  = tid & 7;        // float4 quad within 32-wide K
    const bool doB = (blockIdx.x == 0);

    float4 pa[4], pb[5];
    float asq[4] = {0.f, 0.f, 0.f, 0.f};
    float bsq[5] = {0.f, 0.f, 0.f, 0.f, 0.f};

    auto LDG = [&](int c) {
        size_t kb = (size_t)c * BKF;
        #pragma unroll
        for (int i = 0; i < 4; i++) {              // A: 1024 quads, 4/thread
            int gr = row0 + r8 + 32 * i;
            pa[i] = (gr < BNR) ? *(const float4*)(A + (size_t)gr * HWD + kb + q * 4)
                               : make_float4(0,0,0,0);
        }
        #pragma unroll
        for (int i = 0; i < 5; i++) {              // B: 1280 quads, 5/thread
            int gb = r8 + 32 * i;
            pb[i] = *(const float4*)(Bm + (size_t)gb * HWD + kb + q * 4);
        }
    };

    auto CVTST = [&](int st) {
        uint32_t* s = sm + st * STG_WORDS;
        #pragma unroll
        for (int i = 0; i < 4; i++) {
            float4 v = pa[i];
            asq[i] += v.x*v.x + v.y*v.y + v.z*v.z + v.w*v.w;
            uint4 hv, lv;
            tf32_split(v.x, hv.x, lv.x); tf32_split(v.y, hv.y, lv.y);
            tf32_split(v.z, hv.z, lv.z); tf32_split(v.w, hv.w, lv.w);
            int ar = r8 + 32 * i;
            *(uint4*)(s + SM_AH + ar * 36 + q * 4) = hv;
            *(uint4*)(s + SM_AL + ar * 36 + q * 4) = lv;
        }
        #pragma unroll
        for (int i = 0; i < 5; i++) {
            float4 v = pb[i];
            bsq[i] += v.x*v.x + v.y*v.y + v.z*v.z + v.w*v.w;
            uint4 hv, lv;
            tf32_split(v.x, hv.x, lv.x); tf32_split(v.y, hv.y, lv.y);
            tf32_split(v.z, hv.z, lv.z); tf32_split(v.w, hv.w, lv.w);
            int br = r8 + 32 * i;
            *(uint4*)(s + SM_BH + br * 36 + q * 4) = hv;
            *(uint4*)(s + SM_BL + br * 36 + q * 4) = lv;
        }
    };

    float acc[2][10][4];
    #pragma unroll
    for (int f = 0; f < 2; f++)
        #pragma unroll
        for (int nf = 0; nf < 10; nf++)
            #pragma unroll
            for (int e = 0; e < 4; e++) acc[f][nf][e] = 0.f;

    auto COMP = [&](int st) {
        uint32_t* s = sm + st * STG_WORDS;
        #pragma unroll
        for (int ks = 0; ks < 4; ks++) {
            int k0 = ks * 8;
            uint32_t ah[2][4], al[2][4];
            #pragma unroll
            for (int f = 0; f < 2; f++) {
                int m0 = wm * 32 + f * 16 + lr;
                ah[f][0] = s[SM_AH + (m0    ) * 36 + k0 + lc];
                ah[f][1] = s[SM_AH + (m0 + 8) * 36 + k0 + lc];
                ah[f][2] = s[SM_AH + (m0    ) * 36 + k0 + lc + 4];
                ah[f][3] = s[SM_AH + (m0 + 8) * 36 + k0 + lc + 4];
                al[f][0] = s[SM_AL + (m0    ) * 36 + k0 + lc];
                al[f][1] = s[SM_AL + (m0 + 8) * 36 + k0 + lc];
                al[f][2] = s[SM_AL + (m0    ) * 36 + k0 + lc + 4];
                al[f][3] = s[SM_AL + (m0 + 8) * 36 + k0 + lc + 4];
            }
            #pragma unroll
            for (int nf = 0; nf < 10; nf++) {
                int n0 = wn * 80 + nf * 8 + lr;
                uint32_t bh0 = s[SM_BH + n0 * 36 + k0 + lc];
                uint32_t bh1 = s[SM_BH + n0 * 36 + k0 + lc + 4];
                uint32_t bl0 = s[SM_BL + n0 * 36 + k0 + lc];
                uint32_t bl1 = s[SM_BL + n0 * 36 + k0 + lc + 4];
                #pragma unroll
                for (int f = 0; f < 2; f++) {
                    MMA1688(acc[f][nf], ah[f], bh0, bh1);
                    MMA1688(acc[f][nf], ah[f], bl0, bl1);
                    MMA1688(acc[f][nf], al[f], bh0, bh1);
                }
            }
        }
    };

    LDG(cbeg);
    CVTST(0);
    __syncthreads();

    for (int c = cbeg; c < cend; c++) {
        int st = (c - cbeg) & 1;
        bool more = (c + 1 < cend);
        if (more) LDG(c + 1);
        COMP(st);
        if (more) CVTST(st ^ 1);
        __syncthreads();
    }

    // ---- norm partial reduce: 8 consecutive threads share a row
    #pragma unroll
    for (int i = 0; i < 4; i++) {
        float sv = asq[i];
        #pragma unroll
        for (int o = 4; o; o >>= 1) sv += __shfl_down_sync(0xffffffffu, sv, o, 8);
        if (q == 0) {
            int gr = row0 + r8 + 32 * i;
            if (gr < BNR) g_pnp[z * BNR + gr] = sv;
        }
    }
    if (doB) {
        #pragma unroll
        for (int i = 0; i < 5; i++) {
            float sv = bsq[i];
            #pragma unroll
            for (int o = 4; o; o >>= 1) sv += __shfl_down_sync(0xffffffffu, sv, o, 8);
            if (q == 0) g_tnp[z * TT + r8 + 32 * i] = sv;
        }
    }

    // ---- epilogue: write dot-product partials
    #pragma unroll
    for (int f = 0; f < 2; f++) {
        int grow0 = row0 + wm * 32 + f * 16 + lr;
        #pragma unroll
        for (int nf = 0; nf < 10; nf++) {
            int col = wn * 80 + nf * 8 + lc * 2;
            if (grow0 < BNR) {
                float* o = g_part + ((size_t)z * BNR + grow0) * TT + col;
                o[0] = acc[f][nf][0]; o[1] = acc[f][nf][1];
            }
            if (grow0 + 8 < BNR) {
                float* o = g_part + ((size_t)z * BNR + grow0 + 8) * TT + col;
                o[0] = acc[f][nf][2]; o[1] = acc[f][nf][3];
            }
        }
    }
}

// ---------------------------------------------------------------------------
// Reduce norm partials (fixed order, deterministic) — R9 version.
// ---------------------------------------------------------------------------
__global__ void reduce_norms_kernel()
{
    int idx = blockIdx.x * blockDim.x + threadIdx.x;
    if (idx < BNR) {
        float s = 0.f;
        #pragma unroll
        for (int z = 0; z < SPLITS; z++) s += g_pnp[z * BNR + idx];
        g_pnorm[idx] = s;
    } else if (idx < BNR + TT) {
        int t = idx - BNR;
        float s = 0.f;
        #pragma unroll
        for (int z = 0; z < SPLITS; z++) s += g_tnp[z * TT + t];
        g_tnorm[t] = s;
    }
}

// ---------------------------------------------------------------------------
// Assemble C = 2 * dice_score + focal class cost (inline), float4-vectorized.
// Fixed-order split-K reduce -> deterministic. (R9 version.)
// ---------------------------------------------------------------------------
__global__ void assemble_kernel(const float* __restrict__ logits,
                                const int* __restrict__ tgt_ids,
                                float* __restrict__ out)
{
    int idx = blockIdx.x * blockDim.x + threadIdx.x;
    if (idx >= BNR*TT/4) return;
    int row = idx / (TT/4), t4 = idx % (TT/4);

    float4 dot = make_float4(0.f, 0.f, 0.f, 0.f);
    #pragma unroll
    for (int s = 0; s < SPLITS; s++) {
        float4 v = *(const float4*)(g_part + ((size_t)s * BNR + row) * TT + t4 * 4);
        dot.x += v.x; dot.y += v.y; dot.z += v.z; dot.w += v.w;
    }
    float pn = g_pnorm[row];
    const float* lrow = logits + row * KCLS;

    float4 res;
    float* dp = (float*)&dot;
    float* rp = (float*)&res;
    #pragma unroll
    for (int e = 0; e < 4; e++) {
        int t = t4 * 4 + e;
        float den = pn + g_tnorm[t];
        float score = -((2.f * dp[e] + 1e-4f) / (den + 1e-4f));
        float x = lrow[tgt_ids[t]];
        float pp = 1.f / (1.f + expf(-x));
        float neg = 0.75f * pp * pp * (-logf(1.f - pp + 1e-8f));
        float pos = 0.25f * (1.f - pp) * (1.f - pp) * (-logf(pp + 1e-8f));
        float c = 2.f * score + (pos - neg);
        if (!isfinite(c)) c = 0.f;
        rp[e] = c;
    }
    *(float4*)(out + (size_t)row * TT + t4 * 4) = res;
}

// ---------------------------------------------------------------------------
// Hungarian (Jonker-Volgenant) — absolute-distance form, fp32 internal,
// REDUX warp reductions. (R9 version — best measured: 25.9us.)
// ---------------------------------------------------------------------------
__device__ __forceinline__ uint32_t f2k(float x)
{
    int b = __float_as_int(x);
    return (uint32_t)b ^ ((b < 0) ? 0xFFFFFFFFu : 0x80000000u);
}
__device__ __forceinline__ float k2f(uint32_t k)
{
    int b = (int)(k ^ (((int)k < 0) ? 0x80000000u : 0xFFFFFFFFu));
    return __int_as_float(b);
}

__global__ void hungarian_kernel(const float* __restrict__ C, float* __restrict__ out)
{
    int b = blockIdx.x;
    int lane = threadIdx.x;

    __shared__ float cost[MT][NN];
    __shared__ float u[MT+1];
    __shared__ int p[NN+1], way[NN+1];

    for (int idx = lane; idx < MT*NN; idx += 32) {
        int r = idx / NN, c = idx % NN;
        cost[r][c] = C[(size_t)(b*NN + c) * TT + b*MT + r];
    }
    for (int j = lane; j <= NN; j += 32) { p[j] = 0; way[j] = 0; }
    for (int j = lane; j <= MT; j += 32) u[j] = 0.0f;
    float v[4] = {0.f, 0.f, 0.f, 0.f};
    const int jcol[4] = {lane + 1, lane + 33, lane + 65, lane + 97};
    const uint32_t KINF = 0xFFFFFFFFu;
    __syncwarp();

    for (int i = 1; i <= MT; i++) {
        uint32_t absk[4] = {KINF, KINF, KINF, KINF};
        float dj[4] = {0.f, 0.f, 0.f, 0.f};
        int usedm = (lane >= 4) ? 8 : 0;       // kk=3 invalid for lane>=4 (j>100)
        float Dprev = 0.f;
        int j0 = 0, i0 = i;

        while (true) {
            if (j0 > 0) {
                int ol = (j0 - 1) & 31, ok = (j0 - 1) >> 5;
                if (lane == ol) {
                    #pragma unroll
                    for (int kk = 0; kk < 4; kk++)
                        if (kk == ok) { usedm |= 1 << kk; dj[kk] = Dprev; }
                }
            }
            float off = Dprev - u[i0];

            #pragma unroll
            for (int kk = 0; kk < 4; kk++) {
                if (!((usedm >> kk) & 1)) {
                    float cur = (cost[i0 - 1][jcol[kk] - 1] - v[kk]) + off;
                    uint32_t ck = f2k(cur);
                    if (ck < absk[kk]) { absk[kk] = ck; way[jcol[kk]] = j0; }
                }
            }

            uint32_t bk = KINF;
            uint32_t bj = NN + 2;
            #pragma unroll
            for (int kk = 0; kk < 4; kk++) {
                if (!((usedm >> kk) & 1) && absk[kk] < bk) {
                    bk = absk[kk]; bj = (uint32_t)jcol[kk];
                }
            }
            uint32_t kmin = __reduce_min_sync(0xffffffffu, bk);
            uint32_t j1 = __reduce_min_sync(0xffffffffu, (bk == kmin) ? bj : 0x7FFFFFFFu);

            Dprev = k2f(kmin);            // S_k = abs[j1]
            j0 = (int)j1;
            i0 = p[j0];
            if (i0 == 0) break;
        }

        float Slast = Dprev;
        if (lane == 0) u[i] += Slast;
        #pragma unroll
        for (int kk = 0; kk < 4; kk++) {
            if (((usedm >> kk) & 1) && !(kk == 3 && lane >= 4)) {
                float du = Slast - dj[kk];
                int r = p[jcol[kk]];       // distinct rows across lanes
                u[r] += du;
                v[kk] -= du;
            }
        }
        __syncwarp();
        if (lane == 0) {                  // augment along way[] chain
            p[0] = i;
            int jj = j0;
            while (jj) { int jp = way[jj]; p[jj] = p[jp]; jj = jp; }
        }
        __syncwarp();
    }

    if (lane == 0) {
        int k = 0;
        for (int j = 1; j <= NN; j++) {
            if (p[j] != 0) {
                out[(size_t)BNR*TT + b*MT + k]            = (float)(j - 1);
                out[(size_t)BNR*TT + BB*MT + b*MT + k]    = (float)(p[j] - 1);
                k++;
            }
        }
    }
}

// ---------------------------------------------------------------------------
extern "C" void kernel_launch(void* const* d_in, const int* in_sizes, int n_in,
                              void* d_out, int out_size)
{
    const float* pred_masks   = (const float*)d_in[0];   // (8,100,160,160)
    const float* pred_logits  = (const float*)d_in[1];   // (8,100,80)
    const float* target_masks = (const float*)d_in[2];   // (160,160,160)
    const int*   tgt_ids      = (const int*)d_in[3];     // (160,)
    float* out = (float*)d_out;                           // C(128000) | rows(160) | cols(160)

    cudaFuncSetAttribute(gemm_tf32, cudaFuncAttributeMaxDynamicSharedMemorySize,
                         SMEM_BYTES);

    gemm_tf32<<<dim3(7, SPLITS), 256, SMEM_BYTES>>>(pred_masks, target_masks);

    reduce_norms_kernel<<<4, 256>>>();

    assemble_kernel<<<(BNR*TT/4 + 255)/256, 256>>>(pred_logits, tgt_ids, out);

    hungarian_kernel<<<BB, 32>>>(out, out);
}